// round 1
// baseline (speedup 1.0000x reference)
#include <cuda_runtime.h>
#include <cstdint>

// Problem constants (fixed shapes: 16384 x 3 fp32 each input).
#define NPTS        16384
#define THREADS     256
#define RPT         4               // sources per thread
#define SRC_PER_BLK (THREADS * RPT) // 1024
#define SRC_TILES   (NPTS / SRC_PER_BLK)   // 16
#define TGT_SLICE   1024
#define TGT_SLICES  (NPTS / TGT_SLICE)     // 16
#define BLKS_PER_DIR (SRC_TILES * TGT_SLICES) // 256
#define MAIN_BLOCKS (2 * BLKS_PER_DIR)        // 512

// Scratch: per-(direction, source point) running min of (|t|^2 - 2 s.t),
// stored as order-preserving uint so atomicMin(uint) == float min.
__device__ unsigned g_min[2 * NPTS];

__device__ __forceinline__ unsigned f2ord(float f) {
    unsigned u = __float_as_uint(f);
    return (u & 0x80000000u) ? ~u : (u | 0x80000000u);
}
__device__ __forceinline__ float ord2f(unsigned u) {
    unsigned v = (u & 0x80000000u) ? (u ^ 0x80000000u) : ~u;
    return __uint_as_float(v);
}

__global__ void chamfer_init() {
    int idx = blockIdx.x * blockDim.x + threadIdx.x;
    if (idx < 2 * NPTS) g_min[idx] = 0xFFFFFFFFu;  // encodes -inf? no: max key == +inf float
}

__global__ void __launch_bounds__(THREADS, 8) chamfer_main(
    const float* __restrict__ pred, const float* __restrict__ tgt)
{
    const int b      = blockIdx.x;
    const int dir    = b >> 8;          // 256 blocks per direction
    const int rem    = b & 255;
    const int stile  = rem >> 4;        // 16 source tiles
    const int tslice = rem & 15;        // 16 target slices

    const float* __restrict__ S = dir ? tgt : pred;
    const float* __restrict__ T = dir ? pred : tgt;
    unsigned* gm = g_min + dir * NPTS;

    __shared__ float4 sh[TGT_SLICE];

    // Stage target slice as (-2x, -2y, -2z, |t|^2)
    const int j0 = tslice * TGT_SLICE;
    for (int k = threadIdx.x; k < TGT_SLICE; k += THREADS) {
        const int j = j0 + k;
        float x = T[3 * j + 0];
        float y = T[3 * j + 1];
        float z = T[3 * j + 2];
        sh[k] = make_float4(-2.0f * x, -2.0f * y, -2.0f * z,
                            x * x + y * y + z * z);
    }
    __syncthreads();

    // Load this thread's R source points
    float sx[RPT], sy[RPT], sz[RPT], m[RPT];
    const int i0 = stile * SRC_PER_BLK + threadIdx.x;
#pragma unroll
    for (int r = 0; r < RPT; r++) {
        const int i = i0 + r * THREADS;
        sx[r] = S[3 * i + 0];
        sy[r] = S[3 * i + 1];
        sz[r] = S[3 * i + 2];
        m[r]  = 3.4e38f;
    }

    // Sweep the slice: per pair 3 FFMA + 1 FMNMX
#pragma unroll 4
    for (int k = 0; k < TGT_SLICE; k++) {
        const float4 t = sh[k];
#pragma unroll
        for (int r = 0; r < RPT; r++) {
            float a = fmaf(sx[r], t.x, t.w);
            a = fmaf(sy[r], t.y, a);
            a = fmaf(sz[r], t.z, a);
            m[r] = fminf(m[r], a);
        }
    }

#pragma unroll
    for (int r = 0; r < RPT; r++) {
        atomicMin(&gm[i0 + r * THREADS], f2ord(m[r]));
    }
}

__global__ void chamfer_reduce(const float* __restrict__ pred,
                               const float* __restrict__ tgt,
                               float* __restrict__ out)
{
    __shared__ float red[512];
    float local = 0.0f;
    for (int idx = threadIdx.x; idx < 2 * NPTS; idx += 512) {
        const int dir = idx >> 14;
        const int i   = idx & (NPTS - 1);
        const float* S = dir ? tgt : pred;
        float x = S[3 * i + 0];
        float y = S[3 * i + 1];
        float z = S[3 * i + 2];
        float sn = x * x + y * y + z * z;
        local += ord2f(g_min[idx]) + sn;   // = min_j ||s_i - t_j||^2
    }
    red[threadIdx.x] = local;
    __syncthreads();
    for (int s = 256; s > 0; s >>= 1) {
        if (threadIdx.x < s) red[threadIdx.x] += red[threadIdx.x + s];
        __syncthreads();
    }
    if (threadIdx.x == 0) {
        // (mean_dir0 + mean_dir1) / 2 == total_sum / (2*NPTS)
        out[0] = red[0] / (float)(2 * NPTS);
    }
}

extern "C" void kernel_launch(void* const* d_in, const int* in_sizes, int n_in,
                              void* d_out, int out_size)
{
    const float* pred = (const float*)d_in[0];
    const float* tgt  = (const float*)d_in[1];
    float* out = (float*)d_out;

    chamfer_init<<<(2 * NPTS + 255) / 256, 256>>>();
    chamfer_main<<<MAIN_BLOCKS, THREADS>>>(pred, tgt);
    chamfer_reduce<<<1, 512>>>(pred, tgt, out);
}

// round 3
// speedup vs baseline: 1.0928x; 1.0928x over previous
#include <cuda_runtime.h>
#include <cstdint>

// Fixed shapes: 16384 x 3 fp32 each input.
#define NPTS        16384
#define THREADS     256
#define RPT         4               // sources per thread
#define SRC_PER_BLK (THREADS * RPT) // 1024
#define SRC_TILES   (NPTS / SRC_PER_BLK)   // 16
#define TGT_SLICE   1024
#define TGT_PAIRS   (TGT_SLICE / 2)        // 512 packed target pairs
#define TGT_SLICES  (NPTS / TGT_SLICE)     // 16
#define BLKS_PER_DIR (SRC_TILES * TGT_SLICES) // 256
#define MAIN_BLOCKS (2 * BLKS_PER_DIR)        // 512

// Per-(direction, source point) running min of (|t|^2 - 2 s.t),
// order-preserving uint encoding so atomicMin(uint) == float min.
__device__ unsigned g_min[2 * NPTS];

__device__ __forceinline__ unsigned f2ord(float f) {
    unsigned u = __float_as_uint(f);
    return (u & 0x80000000u) ? ~u : (u | 0x80000000u);
}
__device__ __forceinline__ float ord2f(unsigned u) {
    unsigned v = (u & 0x80000000u) ? (u ^ 0x80000000u) : ~u;
    return __uint_as_float(v);
}

// Packed fp32x2 FMA (Blackwell): d = a*b + c on both 32-bit halves.
__device__ __forceinline__ uint64_t fma2(uint64_t a, uint64_t b, uint64_t c) {
    uint64_t d;
    asm("fma.rn.f32x2 %0, %1, %2, %3;" : "=l"(d) : "l"(a), "l"(b), "l"(c));
    return d;
}
__device__ __forceinline__ void unpack2(uint64_t v, float& lo, float& hi) {
    unsigned l, h;
    asm("mov.b64 {%0, %1}, %2;" : "=r"(l), "=r"(h) : "l"(v));
    lo = __uint_as_float(l);
    hi = __uint_as_float(h);
}
__device__ __forceinline__ uint64_t rep2(float f) {
    uint64_t d;
    unsigned u = __float_as_uint(f);
    asm("mov.b64 %0, {%1, %1};" : "=l"(d) : "r"(u));
    return d;
}

__global__ void chamfer_init() {
    // 32768 uints = 8192 uint4; grid 32 x 256 covers exactly.
    int idx = blockIdx.x * blockDim.x + threadIdx.x;
    ((uint4*)g_min)[idx] =
        make_uint4(0xFFFFFFFFu, 0xFFFFFFFFu, 0xFFFFFFFFu, 0xFFFFFFFFu);
}

__global__ void __launch_bounds__(THREADS, 4) chamfer_main(
    const float* __restrict__ pred, const float* __restrict__ tgt)
{
    const int b      = blockIdx.x;
    const int dir    = b >> 8;          // 256 blocks per direction
    const int rem    = b & 255;
    const int stile  = rem >> 4;        // 16 source tiles
    const int tslice = rem & 15;        // 16 target slices

    const float* __restrict__ S = dir ? tgt : pred;
    const float* __restrict__ T = dir ? pred : tgt;
    unsigned* gm = g_min + dir * NPTS;

    // sh_a[k2] = (-2x0, -2x1, -2y0, -2y1), sh_b[k2] = (-2z0, -2z1, w0, w1)
    __shared__ float4 sh_a[TGT_PAIRS];
    __shared__ float4 sh_b[TGT_PAIRS];

    const int j0 = tslice * TGT_SLICE;
    for (int k = threadIdx.x; k < TGT_SLICE; k += THREADS) {
        const int j = j0 + k;
        float x = T[3 * j + 0];
        float y = T[3 * j + 1];
        float z = T[3 * j + 2];
        float w = x * x + y * y + z * z;
        const int k2 = k >> 1, h = k & 1;
        float* pa = (float*)&sh_a[k2];
        float* pb = (float*)&sh_b[k2];
        pa[h]     = -2.0f * x;
        pa[2 + h] = -2.0f * y;
        pb[h]     = -2.0f * z;
        pb[2 + h] = w;
    }
    __syncthreads();

    // This thread's RPT source points, replicated into both f32x2 halves.
    uint64_t sx2[RPT], sy2[RPT], sz2[RPT];
    float m0[RPT], m1[RPT];
    const int i0 = stile * SRC_PER_BLK + threadIdx.x;
#pragma unroll
    for (int r = 0; r < RPT; r++) {
        const int i = i0 + r * THREADS;
        sx2[r] = rep2(S[3 * i + 0]);
        sy2[r] = rep2(S[3 * i + 1]);
        sz2[r] = rep2(S[3 * i + 2]);
        m0[r] = 3.4e38f;
        m1[r] = 3.4e38f;
    }

    // Per packed iter: 8 pairs via 12 FFMA2 (fma pipe) + 8 FMNMX (alu pipe).
#pragma unroll 2
    for (int k2 = 0; k2 < TGT_PAIRS; k2++) {
        const ulonglong2 A = *reinterpret_cast<const ulonglong2*>(&sh_a[k2]); // x01, y01
        const ulonglong2 B = *reinterpret_cast<const ulonglong2*>(&sh_b[k2]); // z01, w01
#pragma unroll
        for (int r = 0; r < RPT; r++) {
            uint64_t acc = fma2(sx2[r], A.x, B.y);
            acc = fma2(sy2[r], A.y, acc);
            acc = fma2(sz2[r], B.x, acc);
            float lo, hi;
            unpack2(acc, lo, hi);
            m0[r] = fminf(m0[r], lo);
            m1[r] = fminf(m1[r], hi);
        }
    }

#pragma unroll
    for (int r = 0; r < RPT; r++) {
        atomicMin(&gm[i0 + r * THREADS], f2ord(fminf(m0[r], m1[r])));
    }
}

__global__ void chamfer_reduce(const float* __restrict__ pred,
                               const float* __restrict__ tgt,
                               float* __restrict__ out)
{
    __shared__ float red[512];
    float local = 0.0f;
    for (int idx = threadIdx.x; idx < 2 * NPTS; idx += 512) {
        const int dir = idx >> 14;
        const int i   = idx & (NPTS - 1);
        const float* S = dir ? tgt : pred;
        float x = S[3 * i + 0];
        float y = S[3 * i + 1];
        float z = S[3 * i + 2];
        float sn = x * x + y * y + z * z;
        local += ord2f(g_min[idx]) + sn;   // = min_j ||s_i - t_j||^2
        g_min[idx] = 0xFFFFFFFFu;          // reset for next graph replay
    }
    red[threadIdx.x] = local;
    __syncthreads();
    for (int s = 256; s > 0; s >>= 1) {
        if (threadIdx.x < s) red[threadIdx.x] += red[threadIdx.x + s];
        __syncthreads();
    }
    if (threadIdx.x == 0) {
        // (mean_dir0 + mean_dir1) / 2 == total_sum / (2*NPTS)
        out[0] = red[0] / (float)(2 * NPTS);
    }
}

extern "C" void kernel_launch(void* const* d_in, const int* in_sizes, int n_in,
                              void* d_out, int out_size)
{
    const float* pred = (const float*)d_in[0];
    const float* tgt  = (const float*)d_in[1];
    float* out = (float*)d_out;

    chamfer_init<<<32, 256>>>();
    chamfer_main<<<MAIN_BLOCKS, THREADS>>>(pred, tgt);
    chamfer_reduce<<<1, 512>>>(pred, tgt, out);
}